// round 11
// baseline (speedup 1.0000x reference)
#include <cuda_runtime.h>
#include <cuda_bf16.h>
#include <math.h>
#include <stdint.h>

#define NNODES 512
#define EPSF 1e-8f

// static device scratch
__device__ __align__(16) float g_in1t[3][NNODES * 32];
__device__ __align__(16) float g_in2t[5][NNODES * 32];
__device__ __align__(16) float g_geo[(size_t)NNODES * NNODES * 12];
__device__ __align__(16) float g_b1frag[5120];
__device__ __align__(16) float g_b2frag[5120];
__device__ __align__(16) float g_rad[(size_t)NNODES * NNODES * 160]; // [pair][f*32+c]

struct Params {
    const float* __restrict__ in0;
    const float* __restrict__ in1;
    const float* __restrict__ in2;
    const float* __restrict__ rbf;
    const float* __restrict__ rij;
    const float* __restrict__ w1[5];
    const float* __restrict__ b1[5];
    const float* __restrict__ w2[5];
    const float* __restrict__ b2[5];
    float* __restrict__ out;
};

__device__ __forceinline__ unsigned tf32r(float x) {
    unsigned u;
    asm("cvt.rna.tf32.f32 %0, %1;" : "=r"(u) : "f"(x));
    return u;
}
__device__ __forceinline__ void mma8(float& c0, float& c1, float& c2, float& c3,
                                     uint4 a, uint2 b) {
    asm("mma.sync.aligned.m16n8k8.row.col.f32.tf32.tf32.f32 "
        "{%0,%1,%2,%3},{%4,%5,%6,%7},{%8,%9},{%0,%1,%2,%3};"
        : "+f"(c0), "+f"(c1), "+f"(c2), "+f"(c3)
        : "r"(a.x), "r"(a.y), "r"(a.z), "r"(a.w), "r"(b.x), "r"(b.y));
}

__global__ __launch_bounds__(256) void prep_kernel(
    const float* __restrict__ rij,
    const float* __restrict__ in1,
    const float* __restrict__ in2)
{
    int idx = blockIdx.x * 256 + threadIdx.x;
    if (idx < NNODES * 32) {
        #pragma unroll
        for (int i = 0; i < 3; i++) g_in1t[i][idx] = in1[idx * 3 + i];
        #pragma unroll
        for (int i = 0; i < 5; i++) g_in2t[i][idx] = in2[idx * 5 + i];
    }
    const float inv_c2 = 0.28867513459481287f;
    float rx = rij[idx * 3 + 0];
    float ry = rij[idx * 3 + 1];
    float rz = rij[idx * 3 + 2];
    float n2 = rx * rx + ry * ry + rz * rz;
    float nrm = sqrtf(n2);
    float invn = 1.f / (nrm + EPSF);
    float mask = (nrm >= EPSF) ? 1.f : 0.f;
    float ir2 = 1.f / fmaxf(n2, EPSF);
    float* g = g_geo + (size_t)idx * 12;
    g[0] = rx * invn; g[1] = ry * invn; g[2] = rz * invn;
    g[3] = rx * ry * ir2;
    g[4] = ry * rz * ir2;
    g[5] = (2.f * rz * rz - rx * rx - ry * ry) * ir2 * inv_c2;
    g[6] = rz * rx * ir2;
    g[7] = (rx * rx - ry * ry) * 0.5f * ir2;
    g[8] = mask;
    g[9] = 0.f; g[10] = 0.f; g[11] = 0.f;
}

// tf32 B-fragments; B[k][n] = W[n][k]
__global__ void prep_bfrag(Params p) {
    int idx = blockIdx.x * 512 + threadIdx.x;
    if (idx >= 5120) return;
    int i    = idx & 1;
    int lane = (idx >> 1) & 31;
    int nt   = (idx >> 6) & 3;
    int kt   = (idx >> 8) & 3;
    int f    = idx >> 10;
    int g = lane >> 2, t = lane & 3;
    int rw = nt * 8 + g;
    int cw = kt * 8 + t + 4 * i;
    g_b1frag[idx] = __uint_as_float(tf32r(p.w1[f][rw * 32 + cw]));
    g_b2frag[idx] = __uint_as_float(tf32r(p.w2[f][rw * 32 + cw]));
}

// Phase A: radial MLP as independent warp tasks (16-row slab x filter),
// tf32 2-term split MMA, writes g_rad.
__global__ __launch_bounds__(128) void mlp_kernel(Params p) {
    __shared__ float As[4][2][512];
    const int tid  = threadIdx.x;
    const int lane = tid & 31;
    const int w    = tid >> 5;
    const int task = blockIdx.x * 4 + w;   // 0..81919
    const int f    = task % 5;
    const int slab = task / 5;             // 0..16383
    const int g    = lane >> 2;
    const int t4   = lane & 3;

    // weight fragments
    uint2 b1h[4][4], b2h[4][4];
    #pragma unroll
    for (int kt = 0; kt < 4; kt++)
        #pragma unroll
        for (int nt = 0; nt < 4; nt++) {
            int base = (((f * 4 + kt) * 4 + nt) * 64) + lane * 2;
            float2 v1 = *(const float2*)&g_b1frag[base];
            float2 v2 = *(const float2*)&g_b2frag[base];
            b1h[kt][nt] = make_uint2(__float_as_uint(v1.x), __float_as_uint(v1.y));
            b2h[kt][nt] = make_uint2(__float_as_uint(v2.x), __float_as_uint(v2.y));
        }
    float b1v[4][2], b2v[4][2];
    #pragma unroll
    for (int nt = 0; nt < 4; nt++) {
        b1v[nt][0] = p.b1[f][nt * 8 + 2 * t4];
        b1v[nt][1] = p.b1[f][nt * 8 + 2 * t4 + 1];
        b2v[nt][0] = p.b2[f][nt * 8 + 2 * t4];
        b2v[nt][1] = p.b2[f][nt * 8 + 2 * t4 + 1];
    }

    float* A0 = As[w][0];
    float* A1 = As[w][1];
    const float* rsrc = p.rbf + (size_t)slab * 512;

    // split rbf slab -> tf32 hi/lo in A-frag layout
    #pragma unroll
    for (int j = 0; j < 4; j++) {
        int unit = lane + 32 * j;
        int nb = unit >> 3;
        int r0 = (unit & 7) * 4;
        float4 rv = *(const float4*)(rsrc + nb * 32 + r0);
        float xv[4] = {rv.x, rv.y, rv.z, rv.w};
        #pragma unroll
        for (int jj = 0; jj < 4; jj++) {
            int r = r0 + jj;
            unsigned hb = tf32r(xv[jj]);
            float hf = __uint_as_float(hb);
            unsigned lb = tf32r(xv[jj] - hf);
            int kt = r >> 3, rm = r & 7;
            int tq = rm & 3, dl = rm >> 2;
            int off = kt * 128 + ((nb & 7) * 4 + tq) * 4 + (nb >> 3) + 2 * dl;
            A0[off] = hf;
            A1[off] = __uint_as_float(lb);
        }
    }
    __syncwarp();

    // stage1: H = relu(b1 + rbf @ W1^T)
    float acc[4][4];
    #pragma unroll
    for (int nt = 0; nt < 4; nt++) { acc[nt][0]=0.f; acc[nt][1]=0.f; acc[nt][2]=0.f; acc[nt][3]=0.f; }
    #pragma unroll
    for (int kt = 0; kt < 4; kt++) {
        uint4 ah = *(const uint4*)&A0[kt * 128 + lane * 4];
        uint4 al = *(const uint4*)&A1[kt * 128 + lane * 4];
        #pragma unroll
        for (int nt = 0; nt < 4; nt++) {
            mma8(acc[nt][0], acc[nt][1], acc[nt][2], acc[nt][3], ah, b1h[kt][nt]);
            mma8(acc[nt][0], acc[nt][1], acc[nt][2], acc[nt][3], al, b1h[kt][nt]);
        }
    }
    __syncwarp();
    // H epilogue into A0/A1 (overwrite, rbf frags dead)
    #pragma unroll
    for (int nt = 0; nt < 4; nt++) {
        #pragma unroll
        for (int e = 0; e < 4; e++) {
            int row = g + (e >= 2 ? 8 : 0);
            int dc  = e & 1;
            float h = fmaxf(acc[nt][e] + b1v[nt][dc], 0.f);
            unsigned hb = tf32r(h);
            float hf = __uint_as_float(hb);
            unsigned lb = tf32r(h - hf);
            int rm = 2 * t4 + dc;
            int tq = rm & 3, dl = rm >> 2;
            int off = nt * 128 + ((row & 7) * 4 + tq) * 4 + (row >> 3) + 2 * dl;
            A0[off] = hf;
            A1[off] = __uint_as_float(lb);
        }
    }
    __syncwarp();

    // stage2: rad = b2 + H @ W2^T
    #pragma unroll
    for (int nt = 0; nt < 4; nt++) { acc[nt][0]=0.f; acc[nt][1]=0.f; acc[nt][2]=0.f; acc[nt][3]=0.f; }
    #pragma unroll
    for (int kt = 0; kt < 4; kt++) {
        uint4 ah = *(const uint4*)&A0[kt * 128 + lane * 4];
        uint4 al = *(const uint4*)&A1[kt * 128 + lane * 4];
        #pragma unroll
        for (int nt = 0; nt < 4; nt++) {
            mma8(acc[nt][0], acc[nt][1], acc[nt][2], acc[nt][3], ah, b2h[kt][nt]);
            mma8(acc[nt][0], acc[nt][1], acc[nt][2], acc[nt][3], al, b2h[kt][nt]);
        }
    }
    // write rad: rows g and g+8, cols f*32 + nt*8 + 2*t4 (+1)
    #pragma unroll
    for (int nt = 0; nt < 4; nt++) {
        float2 lo2 = make_float2(acc[nt][0] + b2v[nt][0], acc[nt][1] + b2v[nt][1]);
        float2 hi2 = make_float2(acc[nt][2] + b2v[nt][0], acc[nt][3] + b2v[nt][1]);
        size_t rb_ = ((size_t)slab * 16 + g) * 160 + f * 32 + nt * 8 + 2 * t4;
        *(float2*)&g_rad[rb_]            = lo2;
        *(float2*)&g_rad[rb_ + 8 * 160]  = hi2;
    }
}

// Phase B: streaming aggregation. 20 warps = 5 component groups x 4 b-slices.
__global__ __launch_bounds__(640) void agg_kernel(Params p) {
    const int tid  = threadIdx.x;
    const int lane = tid & 31;
    const int wid  = tid >> 5;      // 0..19
    const int f    = wid % 5;
    const int slice= wid / 5;       // 0..3
    const int a    = blockIdx.x;
    const int c    = lane;

    float acc0 = 0.f, acc1 = 0.f, acc2 = 0.f, acc3 = 0.f, acc4 = 0.f;
    const size_t pbase = (size_t)a * NNODES;
    const int bS = slice * 128;

    if (f == 0) {
        #pragma unroll 4
        for (int i = 0; i < 128; i++) {
            int b = bS + i;
            float r00 = __ldg(&g_rad[(pbase + b) * 160 + c]);
            int gi = b * 32 + c;
            acc0 = fmaf(r00, g_in2t[0][gi], acc0);
            acc1 = fmaf(r00, g_in2t[1][gi], acc1);
            acc2 = fmaf(r00, g_in2t[2][gi], acc2);
            acc3 = fmaf(r00, g_in2t[3][gi], acc3);
            acc4 = fmaf(r00, g_in2t[4][gi], acc4);
        }
    } else if (f == 1) {
        #pragma unroll 4
        for (int i = 0; i < 128; i++) {
            int b = bS + i;
            const float* gg = &g_geo[(pbase + b) * 12];
            int gi = b * 32 + c;
            float rx = __ldg(&g_rad[(pbase + b) * 160 + 64 + c]) * __ldg(gg + 8)
                     * __ldg(&p.in0[gi]);
            acc0 = fmaf(rx, __ldg(gg + 3), acc0);
            acc1 = fmaf(rx, __ldg(gg + 4), acc1);
            acc2 = fmaf(rx, __ldg(gg + 5), acc2);
            acc3 = fmaf(rx, __ldg(gg + 6), acc3);
            acc4 = fmaf(rx, __ldg(gg + 7), acc4);
        }
    } else if (f == 2) {
        #pragma unroll 4
        for (int i = 0; i < 128; i++) {
            int b = bS + i;
            float r00 = __ldg(&g_rad[(pbase + b) * 160 + c]);
            int gi = b * 32 + c;
            acc0 = fmaf(r00, g_in1t[0][gi], acc0);
            acc1 = fmaf(r00, g_in1t[1][gi], acc1);
            acc2 = fmaf(r00, g_in1t[2][gi], acc2);
            acc3 = fmaf(r00, __ldg(&p.in0[gi]), acc3);
        }
    } else if (f == 3) {
        #pragma unroll 4
        for (int i = 0; i < 128; i++) {
            int b = bS + i;
            const float* gg = &g_geo[(pbase + b) * 12];
            int gi = b * 32 + c;
            float mask = __ldg(gg + 8);
            const float* rr = &g_rad[(pbase + b) * 160];
            float r10 = __ldg(rr + 96 + c) * mask;
            float r11 = __ldg(rr + 128 + c) * mask;
            float v0 = g_in1t[0][gi];
            float v1 = g_in1t[1][gi];
            float v2 = g_in1t[2][gi];
            float ux = __ldg(gg + 0), uy = __ldg(gg + 1), uz = __ldg(gg + 2);
            acc0 = fmaf(r11, uy * v2 - uz * v1, acc0);
            acc1 = fmaf(r11, uz * v0 - ux * v2, acc1);
            acc2 = fmaf(r11, ux * v1 - uy * v0, acc2);
            acc3 = fmaf(r10, ux * v0 + uy * v1 + uz * v2, acc3);
        }
    } else {
        #pragma unroll 4
        for (int i = 0; i < 128; i++) {
            int b = bS + i;
            const float* gg = &g_geo[(pbase + b) * 12];
            int gi = b * 32 + c;
            float rx = __ldg(&g_rad[(pbase + b) * 160 + 32 + c]) * __ldg(gg + 8)
                     * __ldg(&p.in0[gi]);
            acc0 = fmaf(rx, __ldg(gg + 0), acc0);
            acc1 = fmaf(rx, __ldg(gg + 1), acc1);
            acc2 = fmaf(rx, __ldg(gg + 2), acc2);
        }
    }

    // reduce 4 slices -> slice 0
    __shared__ float red[15 * 32 * 5];
    if (slice > 0) {
        int idx = ((slice - 1) * 5 + f) * 160 + lane * 5;
        red[idx + 0] = acc0; red[idx + 1] = acc1; red[idx + 2] = acc2;
        red[idx + 3] = acc3; red[idx + 4] = acc4;
    }
    __syncthreads();
    if (slice == 0) {
        #pragma unroll
        for (int s = 0; s < 3; s++) {
            int idx = (s * 5 + f) * 160 + lane * 5;
            acc0 += red[idx + 0]; acc1 += red[idx + 1]; acc2 += red[idx + 2];
            acc3 += red[idx + 3]; acc4 += red[idx + 4];
        }
        float* out = p.out;
        if (f == 0) {
            size_t base = 180224 + (((size_t)(NNODES + a)) * 32 + c) * 5;
            out[base + 0] = acc0; out[base + 1] = acc1; out[base + 2] = acc2;
            out[base + 3] = acc3; out[base + 4] = acc4;
        } else if (f == 1) {
            size_t base = 180224 + (((size_t)a) * 32 + c) * 5;
            out[base + 0] = acc0; out[base + 1] = acc1; out[base + 2] = acc2;
            out[base + 3] = acc3; out[base + 4] = acc4;
        } else if (f == 2) {
            size_t base = 32768 + (((size_t)(NNODES + a)) * 32 + c) * 3;
            out[base + 0] = acc0; out[base + 1] = acc1; out[base + 2] = acc2;
            out[(size_t)a * 32 + c] = acc3;
        } else if (f == 3) {
            size_t base = 32768 + (((size_t)(2 * NNODES + a)) * 32 + c) * 3;
            out[base + 0] = acc0; out[base + 1] = acc1; out[base + 2] = acc2;
            out[16384 + (size_t)a * 32 + c] = acc3;
        } else {
            size_t base = 32768 + (((size_t)a) * 32 + c) * 3;
            out[base + 0] = acc0; out[base + 1] = acc1; out[base + 2] = acc2;
        }
    }
}

extern "C" void kernel_launch(void* const* d_in, const int* in_sizes, int n_in,
                              void* d_out, int out_size) {
    Params p;
    p.in0 = (const float*)d_in[0];
    p.in1 = (const float*)d_in[1];
    p.in2 = (const float*)d_in[2];
    p.rbf = (const float*)d_in[3];
    p.rij = (const float*)d_in[4];
    for (int f = 0; f < 5; f++) {
        p.w1[f] = (const float*)d_in[5 + 4 * f];
        p.b1[f] = (const float*)d_in[6 + 4 * f];
        p.w2[f] = (const float*)d_in[7 + 4 * f];
        p.b2[f] = (const float*)d_in[8 + 4 * f];
    }
    p.out = (float*)d_out;

    prep_kernel<<<(NNODES * NNODES) / 256, 256>>>(p.rij, p.in1, p.in2);
    prep_bfrag<<<10, 512>>>(p);
    mlp_kernel<<<NNODES * NNODES / 16 * 5 / 4, 128>>>(p);   // 20480 blocks
    agg_kernel<<<NNODES, 640>>>(p);
}

// round 12
// speedup vs baseline: 1.9295x; 1.9295x over previous
#include <cuda_runtime.h>
#include <cuda_bf16.h>
#include <math.h>
#include <stdint.h>

#define NNODES 512
#define EPSF 1e-8f
#define OUTSZ 344064
#define RADP2 36

// static device scratch
__device__ __align__(16) float g_in1t[3][NNODES * 32];
__device__ __align__(16) float g_in2t[5][NNODES * 32];
__device__ __align__(16) float g_geo[(size_t)NNODES * NNODES * 12];
__device__ __align__(16) float g_b1frag[5120];
__device__ __align__(16) float g_b2frag[5120];
__device__ __align__(16) float g_part[2 * OUTSZ];

struct Params {
    const float* __restrict__ in0;
    const float* __restrict__ in1;
    const float* __restrict__ in2;
    const float* __restrict__ rbf;
    const float* __restrict__ rij;
    const float* __restrict__ w1[5];
    const float* __restrict__ b1[5];
    const float* __restrict__ w2[5];
    const float* __restrict__ b2[5];
    float* __restrict__ out;
};

__device__ __forceinline__ unsigned tf32r(float x) {
    unsigned u;
    asm("cvt.rna.tf32.f32 %0, %1;" : "=r"(u) : "f"(x));
    return u;
}
__device__ __forceinline__ void mma8(float& c0, float& c1, float& c2, float& c3,
                                     uint4 a, uint2 b) {
    asm("mma.sync.aligned.m16n8k8.row.col.f32.tf32.tf32.f32 "
        "{%0,%1,%2,%3},{%4,%5,%6,%7},{%8,%9},{%0,%1,%2,%3};"
        : "+f"(c0), "+f"(c1), "+f"(c2), "+f"(c3)
        : "r"(a.x), "r"(a.y), "r"(a.z), "r"(a.w), "r"(b.x), "r"(b.y));
}
// volatile 64-bit load: prevents hoisting weight frags into long-lived regs
__device__ __forceinline__ uint2 ldg64v(const float* p) {
    uint2 v;
    asm volatile("ld.global.nc.v2.u32 {%0,%1}, [%2];"
                 : "=r"(v.x), "=r"(v.y) : "l"(p));
    return v;
}
__device__ __forceinline__ void cpa16(void* dst, const void* src) {
    unsigned int d = (unsigned int)__cvta_generic_to_shared(dst);
    asm volatile("cp.async.cg.shared.global [%0], [%1], 16;" :: "r"(d), "l"(src));
}
__device__ __forceinline__ void cpa_commit() { asm volatile("cp.async.commit_group;"); }
__device__ __forceinline__ void cpa_wait0()  { asm volatile("cp.async.wait_group 0;" ::: "memory"); }

__global__ __launch_bounds__(256) void prep_kernel(
    const float* __restrict__ rij,
    const float* __restrict__ in1,
    const float* __restrict__ in2)
{
    int idx = blockIdx.x * 256 + threadIdx.x;
    if (idx < NNODES * 32) {
        #pragma unroll
        for (int i = 0; i < 3; i++) g_in1t[i][idx] = in1[idx * 3 + i];
        #pragma unroll
        for (int i = 0; i < 5; i++) g_in2t[i][idx] = in2[idx * 5 + i];
    }
    const float inv_c2 = 0.28867513459481287f;
    float rx = rij[idx * 3 + 0];
    float ry = rij[idx * 3 + 1];
    float rz = rij[idx * 3 + 2];
    float n2 = rx * rx + ry * ry + rz * rz;
    float nrm = sqrtf(n2);
    float invn = 1.f / (nrm + EPSF);
    float mask = (nrm >= EPSF) ? 1.f : 0.f;
    float ir2 = 1.f / fmaxf(n2, EPSF);
    float* g = g_geo + (size_t)idx * 12;
    g[0] = rx * invn; g[1] = ry * invn; g[2] = rz * invn;
    g[3] = rx * ry * ir2;
    g[4] = ry * rz * ir2;
    g[5] = (2.f * rz * rz - rx * rx - ry * ry) * ir2 * inv_c2;
    g[6] = rz * rx * ir2;
    g[7] = (rx * rx - ry * ry) * 0.5f * ir2;
    g[8] = mask;
    g[9] = 0.f; g[10] = 0.f; g[11] = 0.f;
}

__global__ void prep_bfrag(Params p) {
    int idx = blockIdx.x * 512 + threadIdx.x;
    if (idx >= 5120) return;
    int i    = idx & 1;
    int lane = (idx >> 1) & 31;
    int nt   = (idx >> 6) & 3;
    int kt   = (idx >> 8) & 3;
    int f    = idx >> 10;
    int g = lane >> 2, t = lane & 3;
    int rw = nt * 8 + g;
    int cw = kt * 8 + t + 4 * i;
    g_b1frag[idx] = __uint_as_float(tf32r(p.w1[f][rw * 32 + cw]));
    g_b2frag[idx] = __uint_as_float(tf32r(p.w2[f][rw * 32 + cw]));
}

// Fused: 1024 blocks (a, half). 5 warps = 5 filters. 16 tiles x 16 neighbors.
__global__ __launch_bounds__(160, 5) void tfn_kernel(Params p) {
    __shared__ float raw_s[2][512];
    __shared__ float geo_s[2][192];
    __shared__ float As[2][512];
    __shared__ float HR[5][1024];   // frags Hh[0..511] Hl[512..1023]; rad overwrites [b*36+c]
    __shared__ float bias_s[5][64]; // [f][0..31]=b1, [32..63]=b2

    const int tid  = threadIdx.x;
    const int lane = tid & 31;
    const int f    = tid >> 5;
    const int a    = blockIdx.x >> 1;
    const int half = blockIdx.x & 1;
    const int bstart = half * 256;
    const int c    = lane;
    const int g    = lane >> 2;
    const int t4   = lane & 3;

    // biases into smem
    bias_s[f][lane]      = p.b1[f][lane];
    bias_s[f][32 + lane] = p.b2[f][lane];

    float acc0 = 0.f, acc1 = 0.f, acc2 = 0.f, acc3 = 0.f, acc4 = 0.f;

    const float* rbase = p.rbf + ((size_t)a * NNODES + bstart) * 32;
    const float* gbase = g_geo + ((size_t)a * NNODES + bstart) * 12;

    // preload tile 0
    if (tid < 128) {
        cpa16(&raw_s[0][tid * 4], rbase + tid * 4);
    } else {
        int q = tid - 128;
        cpa16(&geo_s[0][q * 4], gbase + q * 4);
        if (q < 16) cpa16(&geo_s[0][(q + 32) * 4], gbase + (q + 32) * 4);
    }
    cpa_commit();
    cpa_wait0();
    __syncthreads();

    for (int t = 0; t < 16; t++) {
        const int cur = t & 1;
        const int b0 = bstart + t * 16;

        // prefetch tile t+1
        if (t < 15) {
            const float* rsrc = rbase + (size_t)(t + 1) * 512;
            const float* gsrc = gbase + (size_t)(t + 1) * 192;
            if (tid < 128) {
                cpa16(&raw_s[cur ^ 1][tid * 4], rsrc + tid * 4);
            } else {
                int q = tid - 128;
                cpa16(&geo_s[cur ^ 1][q * 4], gsrc + q * 4);
                if (q < 16) cpa16(&geo_s[cur ^ 1][(q + 32) * 4], gsrc + (q + 32) * 4);
            }
        }
        cpa_commit();

        // split raw rbf -> tf32 hi/lo A-frags
        if (tid < 128) {
            float4 rv = *(const float4*)&raw_s[cur][tid * 4];
            int nb = tid >> 3;
            int r0 = (tid & 7) * 4;
            float xv[4] = {rv.x, rv.y, rv.z, rv.w};
            #pragma unroll
            for (int j = 0; j < 4; j++) {
                int r = r0 + j;
                unsigned hb = tf32r(xv[j]);
                float hf = __uint_as_float(hb);
                unsigned lb = tf32r(xv[j] - hf);
                int kt = r >> 3, rm = r & 7;
                int tq = rm & 3, dl = rm >> 2;
                int off = kt * 128 + ((nb & 7) * 4 + tq) * 4 + (nb >> 3) + 2 * dl;
                As[0][off] = hf;
                As[1][off] = __uint_as_float(lb);
            }
        }
        __syncthreads();

        // stage1: H = relu(b1 + rbf @ W1^T)
        {
            float acc[4][4];
            #pragma unroll
            for (int nt = 0; nt < 4; nt++) { acc[nt][0]=0.f; acc[nt][1]=0.f; acc[nt][2]=0.f; acc[nt][3]=0.f; }
            #pragma unroll
            for (int kt = 0; kt < 4; kt++) {
                uint4 ah = *(const uint4*)&As[0][kt * 128 + lane * 4];
                uint4 al = *(const uint4*)&As[1][kt * 128 + lane * 4];
                #pragma unroll
                for (int nt = 0; nt < 4; nt++) {
                    uint2 bw = ldg64v(&g_b1frag[(((f * 4 + kt) * 4 + nt) * 64) + lane * 2]);
                    mma8(acc[nt][0], acc[nt][1], acc[nt][2], acc[nt][3], ah, bw);
                    mma8(acc[nt][0], acc[nt][1], acc[nt][2], acc[nt][3], al, bw);
                }
            }
            float* Hh = HR[f];
            float* Hl = HR[f] + 512;
            #pragma unroll
            for (int nt = 0; nt < 4; nt++) {
                #pragma unroll
                for (int e = 0; e < 4; e++) {
                    int row = g + (e >= 2 ? 8 : 0);
                    int dc  = e & 1;
                    float bb = bias_s[f][nt * 8 + 2 * t4 + dc];
                    float h = fmaxf(acc[nt][e] + bb, 0.f);
                    unsigned hb = tf32r(h);
                    float hf = __uint_as_float(hb);
                    unsigned lb = tf32r(h - hf);
                    int rm = 2 * t4 + dc;
                    int tq = rm & 3, dl = rm >> 2;
                    int off = nt * 128 + ((row & 7) * 4 + tq) * 4 + (row >> 3) + 2 * dl;
                    Hh[off] = hf;
                    Hl[off] = __uint_as_float(lb);
                }
            }
        }
        __syncwarp();

        // stage2: rad = b2 + H @ W2^T  (rad overwrites HR[f] at pitch 36)
        {
            float acc[4][4];
            #pragma unroll
            for (int nt = 0; nt < 4; nt++) { acc[nt][0]=0.f; acc[nt][1]=0.f; acc[nt][2]=0.f; acc[nt][3]=0.f; }
            const float* Hh = HR[f];
            const float* Hl = HR[f] + 512;
            #pragma unroll
            for (int kt = 0; kt < 4; kt++) {
                uint4 ah = *(const uint4*)&Hh[kt * 128 + lane * 4];
                uint4 al = *(const uint4*)&Hl[kt * 128 + lane * 4];
                #pragma unroll
                for (int nt = 0; nt < 4; nt++) {
                    uint2 bw = ldg64v(&g_b2frag[(((f * 4 + kt) * 4 + nt) * 64) + lane * 2]);
                    mma8(acc[nt][0], acc[nt][1], acc[nt][2], acc[nt][3], ah, bw);
                    mma8(acc[nt][0], acc[nt][1], acc[nt][2], acc[nt][3], al, bw);
                }
            }
            #pragma unroll
            for (int nt = 0; nt < 4; nt++) {
                int colw = nt * 8 + 2 * t4;
                float b20 = bias_s[f][32 + colw];
                float b21 = bias_s[f][32 + colw + 1];
                *(float2*)&HR[f][g * RADP2 + colw] =
                    make_float2(acc[nt][0] + b20, acc[nt][1] + b21);
                *(float2*)&HR[f][(g + 8) * RADP2 + colw] =
                    make_float2(acc[nt][2] + b20, acc[nt][3] + b21);
            }
        }
        __syncthreads();

        // accumulate over 16 neighbors
        const float* ge = geo_s[cur];
        if (f == 0) {
            #pragma unroll 4
            for (int b = 0; b < 16; b++) {
                int gi = (b0 + b) * 32 + c;
                float r00 = HR[0][b * RADP2 + c];
                acc0 = fmaf(r00, g_in2t[0][gi], acc0);
                acc1 = fmaf(r00, g_in2t[1][gi], acc1);
                acc2 = fmaf(r00, g_in2t[2][gi], acc2);
                acc3 = fmaf(r00, g_in2t[3][gi], acc3);
                acc4 = fmaf(r00, g_in2t[4][gi], acc4);
            }
        } else if (f == 1) {
            #pragma unroll 4
            for (int b = 0; b < 16; b++) {
                const float* gg = ge + b * 12;
                float rx = HR[2][b * RADP2 + c] * gg[8]
                         * p.in0[(size_t)(b0 + b) * 32 + c];
                acc0 = fmaf(rx, gg[3], acc0);
                acc1 = fmaf(rx, gg[4], acc1);
                acc2 = fmaf(rx, gg[5], acc2);
                acc3 = fmaf(rx, gg[6], acc3);
                acc4 = fmaf(rx, gg[7], acc4);
            }
        } else if (f == 2) {
            #pragma unroll 4
            for (int b = 0; b < 16; b++) {
                int gi = (b0 + b) * 32 + c;
                float r00 = HR[0][b * RADP2 + c];
                acc0 = fmaf(r00, g_in1t[0][gi], acc0);
                acc1 = fmaf(r00, g_in1t[1][gi], acc1);
                acc2 = fmaf(r00, g_in1t[2][gi], acc2);
                acc3 = fmaf(r00, p.in0[gi], acc3);
            }
        } else if (f == 3) {
            #pragma unroll 4
            for (int b = 0; b < 16; b++) {
                int gi = (b0 + b) * 32 + c;
                const float* gg = ge + b * 12;
                float mask = gg[8];
                float r10 = HR[3][b * RADP2 + c] * mask;
                float r11 = HR[4][b * RADP2 + c] * mask;
                float v0 = g_in1t[0][gi];
                float v1 = g_in1t[1][gi];
                float v2 = g_in1t[2][gi];
                float ux = gg[0], uy = gg[1], uz = gg[2];
                acc0 = fmaf(r11, uy * v2 - uz * v1, acc0);
                acc1 = fmaf(r11, uz * v0 - ux * v2, acc1);
                acc2 = fmaf(r11, ux * v1 - uy * v0, acc2);
                acc3 = fmaf(r10, ux * v0 + uy * v1 + uz * v2, acc3);
            }
        } else {
            #pragma unroll 4
            for (int b = 0; b < 16; b++) {
                const float* gg = ge + b * 12;
                float rx = HR[1][b * RADP2 + c] * gg[8]
                         * p.in0[(size_t)(b0 + b) * 32 + c];
                acc0 = fmaf(rx, gg[0], acc0);
                acc1 = fmaf(rx, gg[1], acc1);
                acc2 = fmaf(rx, gg[2], acc2);
            }
        }

        cpa_wait0();
        __syncthreads();
    }

    // write partials
    float* out = g_part + (size_t)half * OUTSZ;
    if (f == 0) {
        size_t base = 180224 + (((size_t)(NNODES + a)) * 32 + c) * 5;
        out[base + 0] = acc0; out[base + 1] = acc1; out[base + 2] = acc2;
        out[base + 3] = acc3; out[base + 4] = acc4;
    } else if (f == 1) {
        size_t base = 180224 + (((size_t)a) * 32 + c) * 5;
        out[base + 0] = acc0; out[base + 1] = acc1; out[base + 2] = acc2;
        out[base + 3] = acc3; out[base + 4] = acc4;
    } else if (f == 2) {
        size_t base = 32768 + (((size_t)(NNODES + a)) * 32 + c) * 3;
        out[base + 0] = acc0; out[base + 1] = acc1; out[base + 2] = acc2;
        out[(size_t)a * 32 + c] = acc3;
    } else if (f == 3) {
        size_t base = 32768 + (((size_t)(2 * NNODES + a)) * 32 + c) * 3;
        out[base + 0] = acc0; out[base + 1] = acc1; out[base + 2] = acc2;
        out[16384 + (size_t)a * 32 + c] = acc3;
    } else {
        size_t base = 32768 + (((size_t)a) * 32 + c) * 3;
        out[base + 0] = acc0; out[base + 1] = acc1; out[base + 2] = acc2;
    }
}

__global__ __launch_bounds__(256) void reduce_kernel(float* __restrict__ out) {
    int i = blockIdx.x * 256 + threadIdx.x;
    out[i] = g_part[i] + g_part[OUTSZ + i];
}

extern "C" void kernel_launch(void* const* d_in, const int* in_sizes, int n_in,
                              void* d_out, int out_size) {
    Params p;
    p.in0 = (const float*)d_in[0];
    p.in1 = (const float*)d_in[1];
    p.in2 = (const float*)d_in[2];
    p.rbf = (const float*)d_in[3];
    p.rij = (const float*)d_in[4];
    for (int f = 0; f < 5; f++) {
        p.w1[f] = (const float*)d_in[5 + 4 * f];
        p.b1[f] = (const float*)d_in[6 + 4 * f];
        p.w2[f] = (const float*)d_in[7 + 4 * f];
        p.b2[f] = (const float*)d_in[8 + 4 * f];
    }
    p.out = (float*)d_out;

    prep_kernel<<<(NNODES * NNODES) / 256, 256>>>(p.rij, p.in1, p.in2);
    prep_bfrag<<<10, 512>>>(p);
    tfn_kernel<<<NNODES * 2, 160>>>(p);
    reduce_kernel<<<OUTSZ / 256, 256>>>(p.out);
}

// round 13
// speedup vs baseline: 1.9922x; 1.0325x over previous
#include <cuda_runtime.h>
#include <cuda_bf16.h>
#include <math.h>
#include <stdint.h>

#define NNODES 512
#define EPSF 1e-8f
#define OUTSZ 344064
#define RADP2 36
#define NSPLIT 4

// static device scratch
__device__ __align__(16) float g_in1t[3][NNODES * 32];
__device__ __align__(16) float g_in2t[5][NNODES * 32];
__device__ __align__(16) float g_geo[(size_t)NNODES * NNODES * 12];
__device__ __align__(16) float g_b1frag[5120];
__device__ __align__(16) float g_b2frag[5120];
__device__ __align__(16) float g_part[NSPLIT * OUTSZ];

struct Params {
    const float* __restrict__ in0;
    const float* __restrict__ in1;
    const float* __restrict__ in2;
    const float* __restrict__ rbf;
    const float* __restrict__ rij;
    const float* __restrict__ w1[5];
    const float* __restrict__ b1[5];
    const float* __restrict__ w2[5];
    const float* __restrict__ b2[5];
    float* __restrict__ out;
};

__device__ __forceinline__ unsigned tf32r(float x) {
    unsigned u;
    asm("cvt.rna.tf32.f32 %0, %1;" : "=r"(u) : "f"(x));
    return u;
}
__device__ __forceinline__ void mma8(float& c0, float& c1, float& c2, float& c3,
                                     uint4 a, uint2 b) {
    asm("mma.sync.aligned.m16n8k8.row.col.f32.tf32.tf32.f32 "
        "{%0,%1,%2,%3},{%4,%5,%6,%7},{%8,%9},{%0,%1,%2,%3};"
        : "+f"(c0), "+f"(c1), "+f"(c2), "+f"(c3)
        : "r"(a.x), "r"(a.y), "r"(a.z), "r"(a.w), "r"(b.x), "r"(b.y));
}
__device__ __forceinline__ uint2 ldg64v(const float* p) {
    uint2 v;
    asm volatile("ld.global.nc.v2.u32 {%0,%1}, [%2];"
                 : "=r"(v.x), "=r"(v.y) : "l"(p));
    return v;
}
__device__ __forceinline__ void cpa16(void* dst, const void* src) {
    unsigned int d = (unsigned int)__cvta_generic_to_shared(dst);
    asm volatile("cp.async.cg.shared.global [%0], [%1], 16;" :: "r"(d), "l"(src));
}
__device__ __forceinline__ void cpa_commit() { asm volatile("cp.async.commit_group;"); }
__device__ __forceinline__ void cpa_wait0()  { asm volatile("cp.async.wait_group 0;" ::: "memory"); }

__global__ __launch_bounds__(256) void prep_kernel(
    const float* __restrict__ rij,
    const float* __restrict__ in1,
    const float* __restrict__ in2)
{
    int idx = blockIdx.x * 256 + threadIdx.x;
    if (idx < NNODES * 32) {
        #pragma unroll
        for (int i = 0; i < 3; i++) g_in1t[i][idx] = in1[idx * 3 + i];
        #pragma unroll
        for (int i = 0; i < 5; i++) g_in2t[i][idx] = in2[idx * 5 + i];
    }
    const float inv_c2 = 0.28867513459481287f;
    float rx = rij[idx * 3 + 0];
    float ry = rij[idx * 3 + 1];
    float rz = rij[idx * 3 + 2];
    float n2 = rx * rx + ry * ry + rz * rz;
    float nrm = sqrtf(n2);
    float invn = 1.f / (nrm + EPSF);
    float mask = (nrm >= EPSF) ? 1.f : 0.f;
    float ir2 = 1.f / fmaxf(n2, EPSF);
    float* g = g_geo + (size_t)idx * 12;
    g[0] = rx * invn; g[1] = ry * invn; g[2] = rz * invn;
    g[3] = rx * ry * ir2;
    g[4] = ry * rz * ir2;
    g[5] = (2.f * rz * rz - rx * rx - ry * ry) * ir2 * inv_c2;
    g[6] = rz * rx * ir2;
    g[7] = (rx * rx - ry * ry) * 0.5f * ir2;
    g[8] = mask;
    g[9] = 0.f; g[10] = 0.f; g[11] = 0.f;
}

__global__ void prep_bfrag(Params p) {
    int idx = blockIdx.x * 512 + threadIdx.x;
    if (idx >= 5120) return;
    int i    = idx & 1;
    int lane = (idx >> 1) & 31;
    int nt   = (idx >> 6) & 3;
    int kt   = (idx >> 8) & 3;
    int f    = idx >> 10;
    int g = lane >> 2, t = lane & 3;
    int rw = nt * 8 + g;
    int cw = kt * 8 + t + 4 * i;
    g_b1frag[idx] = __uint_as_float(tf32r(p.w1[f][rw * 32 + cw]));
    g_b2frag[idx] = __uint_as_float(tf32r(p.w2[f][rw * 32 + cw]));
}

// Fused: 2048 blocks (a, quarter). 5 warps = 5 filters. 8 tiles x 16 neighbors.
__global__ __launch_bounds__(160, 5) void tfn_kernel(Params p) {
    __shared__ float raw_s[2][512];
    __shared__ float geo_s[2][192];
    __shared__ float As[2][512];
    __shared__ float HR[5][1024];   // frags Hh/Hl; rad overwrites [b*36+c]
    __shared__ float bias_s[5][64];

    const int tid  = threadIdx.x;
    const int lane = tid & 31;
    const int f    = tid >> 5;
    const int a    = blockIdx.x >> 2;
    const int part = blockIdx.x & 3;
    const int bstart = part * 128;
    const int c    = lane;
    const int g    = lane >> 2;
    const int t4   = lane & 3;

    bias_s[f][lane]      = p.b1[f][lane];
    bias_s[f][32 + lane] = p.b2[f][lane];

    float acc0 = 0.f, acc1 = 0.f, acc2 = 0.f, acc3 = 0.f, acc4 = 0.f;

    const float* rbase = p.rbf + ((size_t)a * NNODES + bstart) * 32;
    const float* gbase = g_geo + ((size_t)a * NNODES + bstart) * 12;

    // preload tile 0
    if (tid < 128) {
        cpa16(&raw_s[0][tid * 4], rbase + tid * 4);
    } else {
        int q = tid - 128;
        cpa16(&geo_s[0][q * 4], gbase + q * 4);
        if (q < 16) cpa16(&geo_s[0][(q + 32) * 4], gbase + (q + 32) * 4);
    }
    cpa_commit();
    cpa_wait0();
    __syncthreads();

    for (int t = 0; t < 8; t++) {
        const int cur = t & 1;
        const int b0 = bstart + t * 16;

        // prefetch tile t+1
        if (t < 7) {
            const float* rsrc = rbase + (size_t)(t + 1) * 512;
            const float* gsrc = gbase + (size_t)(t + 1) * 192;
            if (tid < 128) {
                cpa16(&raw_s[cur ^ 1][tid * 4], rsrc + tid * 4);
            } else {
                int q = tid - 128;
                cpa16(&geo_s[cur ^ 1][q * 4], gsrc + q * 4);
                if (q < 16) cpa16(&geo_s[cur ^ 1][(q + 32) * 4], gsrc + (q + 32) * 4);
            }
        }
        cpa_commit();

        // split raw rbf -> tf32 hi/lo A-frags
        if (tid < 128) {
            float4 rv = *(const float4*)&raw_s[cur][tid * 4];
            int nb = tid >> 3;
            int r0 = (tid & 7) * 4;
            float xv[4] = {rv.x, rv.y, rv.z, rv.w};
            #pragma unroll
            for (int j = 0; j < 4; j++) {
                int r = r0 + j;
                unsigned hb = tf32r(xv[j]);
                float hf = __uint_as_float(hb);
                unsigned lb = tf32r(xv[j] - hf);
                int kt = r >> 3, rm = r & 7;
                int tq = rm & 3, dl = rm >> 2;
                int off = kt * 128 + ((nb & 7) * 4 + tq) * 4 + (nb >> 3) + 2 * dl;
                As[0][off] = hf;
                As[1][off] = __uint_as_float(lb);
            }
        }
        __syncthreads();

        // stage1: H = relu(b1 + rbf @ W1^T)
        {
            float acc[4][4];
            #pragma unroll
            for (int nt = 0; nt < 4; nt++) { acc[nt][0]=0.f; acc[nt][1]=0.f; acc[nt][2]=0.f; acc[nt][3]=0.f; }
            #pragma unroll
            for (int kt = 0; kt < 4; kt++) {
                uint4 ah = *(const uint4*)&As[0][kt * 128 + lane * 4];
                uint4 al = *(const uint4*)&As[1][kt * 128 + lane * 4];
                #pragma unroll
                for (int nt = 0; nt < 4; nt++) {
                    uint2 bw = ldg64v(&g_b1frag[(((f * 4 + kt) * 4 + nt) * 64) + lane * 2]);
                    mma8(acc[nt][0], acc[nt][1], acc[nt][2], acc[nt][3], ah, bw);
                    mma8(acc[nt][0], acc[nt][1], acc[nt][2], acc[nt][3], al, bw);
                }
            }
            float* Hh = HR[f];
            float* Hl = HR[f] + 512;
            #pragma unroll
            for (int nt = 0; nt < 4; nt++) {
                #pragma unroll
                for (int e = 0; e < 4; e++) {
                    int row = g + (e >= 2 ? 8 : 0);
                    int dc  = e & 1;
                    float bb = bias_s[f][nt * 8 + 2 * t4 + dc];
                    float h = fmaxf(acc[nt][e] + bb, 0.f);
                    unsigned hb = tf32r(h);
                    float hf = __uint_as_float(hb);
                    unsigned lb = tf32r(h - hf);
                    int rm = 2 * t4 + dc;
                    int tq = rm & 3, dl = rm >> 2;
                    int off = nt * 128 + ((row & 7) * 4 + tq) * 4 + (row >> 3) + 2 * dl;
                    Hh[off] = hf;
                    Hl[off] = __uint_as_float(lb);
                }
            }
        }
        __syncwarp();

        // stage2: rad = b2 + H @ W2^T
        {
            float acc[4][4];
            #pragma unroll
            for (int nt = 0; nt < 4; nt++) { acc[nt][0]=0.f; acc[nt][1]=0.f; acc[nt][2]=0.f; acc[nt][3]=0.f; }
            const float* Hh = HR[f];
            const float* Hl = HR[f] + 512;
            #pragma unroll
            for (int kt = 0; kt < 4; kt++) {
                uint4 ah = *(const uint4*)&Hh[kt * 128 + lane * 4];
                uint4 al = *(const uint4*)&Hl[kt * 128 + lane * 4];
                #pragma unroll
                for (int nt = 0; nt < 4; nt++) {
                    uint2 bw = ldg64v(&g_b2frag[(((f * 4 + kt) * 4 + nt) * 64) + lane * 2]);
                    mma8(acc[nt][0], acc[nt][1], acc[nt][2], acc[nt][3], ah, bw);
                    mma8(acc[nt][0], acc[nt][1], acc[nt][2], acc[nt][3], al, bw);
                }
            }
            #pragma unroll
            for (int nt = 0; nt < 4; nt++) {
                int colw = nt * 8 + 2 * t4;
                float b20 = bias_s[f][32 + colw];
                float b21 = bias_s[f][32 + colw + 1];
                *(float2*)&HR[f][g * RADP2 + colw] =
                    make_float2(acc[nt][0] + b20, acc[nt][1] + b21);
                *(float2*)&HR[f][(g + 8) * RADP2 + colw] =
                    make_float2(acc[nt][2] + b20, acc[nt][3] + b21);
            }
        }
        __syncthreads();

        // accumulate over 16 neighbors
        const float* ge = geo_s[cur];
        if (f == 0) {
            #pragma unroll 4
            for (int b = 0; b < 16; b++) {
                int gi = (b0 + b) * 32 + c;
                float r00 = HR[0][b * RADP2 + c];
                acc0 = fmaf(r00, g_in2t[0][gi], acc0);
                acc1 = fmaf(r00, g_in2t[1][gi], acc1);
                acc2 = fmaf(r00, g_in2t[2][gi], acc2);
                acc3 = fmaf(r00, g_in2t[3][gi], acc3);
                acc4 = fmaf(r00, g_in2t[4][gi], acc4);
            }
        } else if (f == 1) {
            #pragma unroll 4
            for (int b = 0; b < 16; b++) {
                const float* gg = ge + b * 12;
                float rx = HR[2][b * RADP2 + c] * gg[8]
                         * p.in0[(size_t)(b0 + b) * 32 + c];
                acc0 = fmaf(rx, gg[3], acc0);
                acc1 = fmaf(rx, gg[4], acc1);
                acc2 = fmaf(rx, gg[5], acc2);
                acc3 = fmaf(rx, gg[6], acc3);
                acc4 = fmaf(rx, gg[7], acc4);
            }
        } else if (f == 2) {
            #pragma unroll 4
            for (int b = 0; b < 16; b++) {
                int gi = (b0 + b) * 32 + c;
                float r00 = HR[0][b * RADP2 + c];
                acc0 = fmaf(r00, g_in1t[0][gi], acc0);
                acc1 = fmaf(r00, g_in1t[1][gi], acc1);
                acc2 = fmaf(r00, g_in1t[2][gi], acc2);
                acc3 = fmaf(r00, p.in0[gi], acc3);
            }
        } else if (f == 3) {
            #pragma unroll 4
            for (int b = 0; b < 16; b++) {
                int gi = (b0 + b) * 32 + c;
                const float* gg = ge + b * 12;
                float mask = gg[8];
                float r10 = HR[3][b * RADP2 + c] * mask;
                float r11 = HR[4][b * RADP2 + c] * mask;
                float v0 = g_in1t[0][gi];
                float v1 = g_in1t[1][gi];
                float v2 = g_in1t[2][gi];
                float ux = gg[0], uy = gg[1], uz = gg[2];
                acc0 = fmaf(r11, uy * v2 - uz * v1, acc0);
                acc1 = fmaf(r11, uz * v0 - ux * v2, acc1);
                acc2 = fmaf(r11, ux * v1 - uy * v0, acc2);
                acc3 = fmaf(r10, ux * v0 + uy * v1 + uz * v2, acc3);
            }
        } else {
            #pragma unroll 4
            for (int b = 0; b < 16; b++) {
                const float* gg = ge + b * 12;
                float rx = HR[1][b * RADP2 + c] * gg[8]
                         * p.in0[(size_t)(b0 + b) * 32 + c];
                acc0 = fmaf(rx, gg[0], acc0);
                acc1 = fmaf(rx, gg[1], acc1);
                acc2 = fmaf(rx, gg[2], acc2);
            }
        }

        cpa_wait0();
        __syncthreads();
    }

    // write partials
    float* out = g_part + (size_t)part * OUTSZ;
    if (f == 0) {
        size_t base = 180224 + (((size_t)(NNODES + a)) * 32 + c) * 5;
        out[base + 0] = acc0; out[base + 1] = acc1; out[base + 2] = acc2;
        out[base + 3] = acc3; out[base + 4] = acc4;
    } else if (f == 1) {
        size_t base = 180224 + (((size_t)a) * 32 + c) * 5;
        out[base + 0] = acc0; out[base + 1] = acc1; out[base + 2] = acc2;
        out[base + 3] = acc3; out[base + 4] = acc4;
    } else if (f == 2) {
        size_t base = 32768 + (((size_t)(NNODES + a)) * 32 + c) * 3;
        out[base + 0] = acc0; out[base + 1] = acc1; out[base + 2] = acc2;
        out[(size_t)a * 32 + c] = acc3;
    } else if (f == 3) {
        size_t base = 32768 + (((size_t)(2 * NNODES + a)) * 32 + c) * 3;
        out[base + 0] = acc0; out[base + 1] = acc1; out[base + 2] = acc2;
        out[16384 + (size_t)a * 32 + c] = acc3;
    } else {
        size_t base = 32768 + (((size_t)a) * 32 + c) * 3;
        out[base + 0] = acc0; out[base + 1] = acc1; out[base + 2] = acc2;
    }
}

__global__ __launch_bounds__(256) void reduce_kernel(float* __restrict__ out) {
    int i = blockIdx.x * 256 + threadIdx.x;
    out[i] = (g_part[i] + g_part[OUTSZ + i])
           + (g_part[2 * OUTSZ + i] + g_part[3 * OUTSZ + i]);
}

extern "C" void kernel_launch(void* const* d_in, const int* in_sizes, int n_in,
                              void* d_out, int out_size) {
    Params p;
    p.in0 = (const float*)d_in[0];
    p.in1 = (const float*)d_in[1];
    p.in2 = (const float*)d_in[2];
    p.rbf = (const float*)d_in[3];
    p.rij = (const float*)d_in[4];
    for (int f = 0; f < 5; f++) {
        p.w1[f] = (const float*)d_in[5 + 4 * f];
        p.b1[f] = (const float*)d_in[6 + 4 * f];
        p.w2[f] = (const float*)d_in[7 + 4 * f];
        p.b2[f] = (const float*)d_in[8 + 4 * f];
    }
    p.out = (float*)d_out;

    prep_kernel<<<(NNODES * NNODES) / 256, 256>>>(p.rij, p.in1, p.in2);
    prep_bfrag<<<10, 512>>>(p);
    tfn_kernel<<<NNODES * NSPLIT, 160>>>(p);
    reduce_kernel<<<OUTSZ / 256, 256>>>(p.out);
}

// round 15
// speedup vs baseline: 2.0118x; 1.0098x over previous
#include <cuda_runtime.h>
#include <cuda_bf16.h>
#include <math.h>
#include <stdint.h>

#define NNODES 512
#define EPSF 1e-8f
#define OUTSZ 344064
#define RADP2 36
#define NSPLIT 8
#define NTILES 4          // tiles per block = (512/NSPLIT)/16

// static device scratch
__device__ __align__(16) float g_in1t[3][NNODES * 32];
__device__ __align__(16) float g_in2t[5][NNODES * 32];
__device__ __align__(16) float g_geo[(size_t)NNODES * NNODES * 12];
__device__ __align__(16) float g_b1frag[5120];
__device__ __align__(16) float g_b2frag[5120];
__device__ __align__(16) float g_part[NSPLIT * OUTSZ];

struct Params {
    const float* __restrict__ in0;
    const float* __restrict__ in1;
    const float* __restrict__ in2;
    const float* __restrict__ rbf;
    const float* __restrict__ rij;
    const float* __restrict__ w1[5];
    const float* __restrict__ b1[5];
    const float* __restrict__ w2[5];
    const float* __restrict__ b2[5];
    float* __restrict__ out;
};

__device__ __forceinline__ unsigned tf32r(float x) {
    unsigned u;
    asm("cvt.rna.tf32.f32 %0, %1;" : "=r"(u) : "f"(x));
    return u;
}
__device__ __forceinline__ void mma8(float& c0, float& c1, float& c2, float& c3,
                                     uint4 a, uint2 b) {
    asm("mma.sync.aligned.m16n8k8.row.col.f32.tf32.tf32.f32 "
        "{%0,%1,%2,%3},{%4,%5,%6,%7},{%8,%9},{%0,%1,%2,%3};"
        : "+f"(c0), "+f"(c1), "+f"(c2), "+f"(c3)
        : "r"(a.x), "r"(a.y), "r"(a.z), "r"(a.w), "r"(b.x), "r"(b.y));
}
__device__ __forceinline__ uint2 ldg64v(const float* p) {
    uint2 v;
    asm volatile("ld.global.nc.v2.u32 {%0,%1}, [%2];"
                 : "=r"(v.x), "=r"(v.y) : "l"(p));
    return v;
}
__device__ __forceinline__ void cpa16(void* dst, const void* src) {
    unsigned int d = (unsigned int)__cvta_generic_to_shared(dst);
    asm volatile("cp.async.cg.shared.global [%0], [%1], 16;" :: "r"(d), "l"(src));
}
__device__ __forceinline__ void cpa_commit() { asm volatile("cp.async.commit_group;"); }
__device__ __forceinline__ void cpa_wait0()  { asm volatile("cp.async.wait_group 0;" ::: "memory"); }

__global__ __launch_bounds__(256) void prep_kernel(
    const float* __restrict__ rij,
    const float* __restrict__ in1,
    const float* __restrict__ in2)
{
    int idx = blockIdx.x * 256 + threadIdx.x;
    if (idx < NNODES * 32) {
        #pragma unroll
        for (int i = 0; i < 3; i++) g_in1t[i][idx] = in1[idx * 3 + i];
        #pragma unroll
        for (int i = 0; i < 5; i++) g_in2t[i][idx] = in2[idx * 5 + i];
    }
    const float inv_c2 = 0.28867513459481287f;
    float rx = rij[idx * 3 + 0];
    float ry = rij[idx * 3 + 1];
    float rz = rij[idx * 3 + 2];
    float n2 = rx * rx + ry * ry + rz * rz;
    float nrm = sqrtf(n2);
    float invn = 1.f / (nrm + EPSF);
    float mask = (nrm >= EPSF) ? 1.f : 0.f;
    float ir2 = 1.f / fmaxf(n2, EPSF);
    float* g = g_geo + (size_t)idx * 12;
    g[0] = rx * invn; g[1] = ry * invn; g[2] = rz * invn;
    g[3] = rx * ry * ir2;
    g[4] = ry * rz * ir2;
    g[5] = (2.f * rz * rz - rx * rx - ry * ry) * ir2 * inv_c2;
    g[6] = rz * rx * ir2;
    g[7] = (rx * rx - ry * ry) * 0.5f * ir2;
    g[8] = mask;
    g[9] = 0.f; g[10] = 0.f; g[11] = 0.f;
}

__global__ void prep_bfrag(Params p) {
    int idx = blockIdx.x * 512 + threadIdx.x;
    if (idx >= 5120) return;
    int i    = idx & 1;
    int lane = (idx >> 1) & 31;
    int nt   = (idx >> 6) & 3;
    int kt   = (idx >> 8) & 3;
    int f    = idx >> 10;
    int g = lane >> 2, t = lane & 3;
    int rw = nt * 8 + g;
    int cw = kt * 8 + t + 4 * i;
    g_b1frag[idx] = __uint_as_float(tf32r(p.w1[f][rw * 32 + cw]));
    g_b2frag[idx] = __uint_as_float(tf32r(p.w2[f][rw * 32 + cw]));
}

// Fused: 4096 blocks (a, eighth). 5 warps = 5 filters. 4 tiles x 16 neighbors.
__global__ __launch_bounds__(160, 5) void tfn_kernel(Params p) {
    __shared__ float raw_s[2][512];
    __shared__ float geo_s[2][192];
    __shared__ float As[2][512];
    __shared__ float HR[5][1024];   // frags Hh/Hl; rad overwrites [b*36+c]
    __shared__ float bias_s[5][64];

    const int tid  = threadIdx.x;
    const int lane = tid & 31;
    const int f    = tid >> 5;
    const int a    = blockIdx.x >> 3;
    const int part = blockIdx.x & 7;
    const int bstart = part * 64;
    const int c    = lane;
    const int g    = lane >> 2;
    const int t4   = lane & 3;

    bias_s[f][lane]      = p.b1[f][lane];
    bias_s[f][32 + lane] = p.b2[f][lane];

    float acc0 = 0.f, acc1 = 0.f, acc2 = 0.f, acc3 = 0.f, acc4 = 0.f;

    const float* rbase = p.rbf + ((size_t)a * NNODES + bstart) * 32;
    const float* gbase = g_geo + ((size_t)a * NNODES + bstart) * 12;

    // preload tile 0
    if (tid < 128) {
        cpa16(&raw_s[0][tid * 4], rbase + tid * 4);
    } else {
        int q = tid - 128;
        cpa16(&geo_s[0][q * 4], gbase + q * 4);
        if (q < 16) cpa16(&geo_s[0][(q + 32) * 4], gbase + (q + 32) * 4);
    }
    cpa_commit();
    cpa_wait0();
    __syncthreads();

    for (int t = 0; t < NTILES; t++) {
        const int cur = t & 1;
        const int b0 = bstart + t * 16;

        // prefetch tile t+1
        if (t < NTILES - 1) {
            const float* rsrc = rbase + (size_t)(t + 1) * 512;
            const float* gsrc = gbase + (size_t)(t + 1) * 192;
            if (tid < 128) {
                cpa16(&raw_s[cur ^ 1][tid * 4], rsrc + tid * 4);
            } else {
                int q = tid - 128;
                cpa16(&geo_s[cur ^ 1][q * 4], gsrc + q * 4);
                if (q < 16) cpa16(&geo_s[cur ^ 1][(q + 32) * 4], gsrc + (q + 32) * 4);
            }
        }
        cpa_commit();

        // split raw rbf -> tf32 hi/lo A-frags
        if (tid < 128) {
            float4 rv = *(const float4*)&raw_s[cur][tid * 4];
            int nb = tid >> 3;
            int r0 = (tid & 7) * 4;
            float xv[4] = {rv.x, rv.y, rv.z, rv.w};
            #pragma unroll
            for (int j = 0; j < 4; j++) {
                int r = r0 + j;
                unsigned hb = tf32r(xv[j]);
                float hf = __uint_as_float(hb);
                unsigned lb = tf32r(xv[j] - hf);
                int kt = r >> 3, rm = r & 7;
                int tq = rm & 3, dl = rm >> 2;
                int off = kt * 128 + ((nb & 7) * 4 + tq) * 4 + (nb >> 3) + 2 * dl;
                As[0][off] = hf;
                As[1][off] = __uint_as_float(lb);
            }
        }
        __syncthreads();

        // stage1: H = relu(b1 + rbf @ W1^T) -- weight frags software-pipelined
        {
            float acc[4][4];
            #pragma unroll
            for (int nt = 0; nt < 4; nt++) { acc[nt][0]=0.f; acc[nt][1]=0.f; acc[nt][2]=0.f; acc[nt][3]=0.f; }
            uint2 bw[4];
            #pragma unroll
            for (int nt = 0; nt < 4; nt++)
                bw[nt] = ldg64v(&g_b1frag[((f * 16 + nt) * 64) + lane * 2]);
            #pragma unroll
            for (int kt = 0; kt < 4; kt++) {
                uint2 nb[4];
                if (kt < 3) {
                    #pragma unroll
                    for (int nt = 0; nt < 4; nt++)
                        nb[nt] = ldg64v(&g_b1frag[(((f * 4 + kt + 1) * 4 + nt) * 64) + lane * 2]);
                }
                uint4 ah = *(const uint4*)&As[0][kt * 128 + lane * 4];
                uint4 al = *(const uint4*)&As[1][kt * 128 + lane * 4];
                #pragma unroll
                for (int nt = 0; nt < 4; nt++) {
                    mma8(acc[nt][0], acc[nt][1], acc[nt][2], acc[nt][3], ah, bw[nt]);
                    mma8(acc[nt][0], acc[nt][1], acc[nt][2], acc[nt][3], al, bw[nt]);
                }
                if (kt < 3) {
                    #pragma unroll
                    for (int nt = 0; nt < 4; nt++) bw[nt] = nb[nt];
                }
            }
            float* Hh = HR[f];
            float* Hl = HR[f] + 512;
            #pragma unroll
            for (int nt = 0; nt < 4; nt++) {
                #pragma unroll
                for (int e = 0; e < 4; e++) {
                    int row = g + (e >= 2 ? 8 : 0);
                    int dc  = e & 1;
                    float bb = bias_s[f][nt * 8 + 2 * t4 + dc];
                    float h = fmaxf(acc[nt][e] + bb, 0.f);
                    unsigned hb = tf32r(h);
                    float hf = __uint_as_float(hb);
                    unsigned lb = tf32r(h - hf);
                    int rm = 2 * t4 + dc;
                    int tq = rm & 3, dl = rm >> 2;
                    int off = nt * 128 + ((row & 7) * 4 + tq) * 4 + (row >> 3) + 2 * dl;
                    Hh[off] = hf;
                    Hl[off] = __uint_as_float(lb);
                }
            }
        }
        __syncwarp();

        // stage2: rad = b2 + H @ W2^T -- weight frags software-pipelined
        {
            float acc[4][4];
            #pragma unroll
            for (int nt = 0; nt < 4; nt++) { acc[nt][0]=0.f; acc[nt][1]=0.f; acc[nt][2]=0.f; acc[nt][3]=0.f; }
            const float* Hh = HR[f];
            const float* Hl = HR[f] + 512;
            uint2 bw[4];
            #pragma unroll
            for (int nt = 0; nt < 4; nt++)
                bw[nt] = ldg64v(&g_b2frag[((f * 16 + nt) * 64) + lane * 2]);
            #pragma unroll
            for (int kt = 0; kt < 4; kt++) {
                uint2 nb[4];
                if (kt < 3) {
                    #pragma unroll
                    for (int nt = 0; nt < 4; nt++)
                        nb[nt] = ldg64v(&g_b2frag[(((f * 4 + kt + 1) * 4 + nt) * 64) + lane * 2]);
                }
                uint4 ah = *(const uint4*)&Hh[kt * 128 + lane * 4];
                uint4 al = *(const uint4*)&Hl[kt * 128 + lane * 4];
                #pragma unroll
                for (int nt = 0; nt < 4; nt++) {
                    mma8(acc[nt][0], acc[nt][1], acc[nt][2], acc[nt][3], ah, bw[nt]);
                    mma8(acc[nt][0], acc[nt][1], acc[nt][2], acc[nt][3], al, bw[nt]);
                }
                if (kt < 3) {
                    #pragma unroll
                    for (int nt = 0; nt < 4; nt++) bw[nt] = nb[nt];
                }
            }
            #pragma unroll
            for (int nt = 0; nt < 4; nt++) {
                int colw = nt * 8 + 2 * t4;
                float b20 = bias_s[f][32 + colw];
                float b21 = bias_s[f][32 + colw + 1];
                *(float2*)&HR[f][g * RADP2 + colw] =
                    make_float2(acc[nt][0] + b20, acc[nt][1] + b21);
                *(float2*)&HR[f][(g + 8) * RADP2 + colw] =
                    make_float2(acc[nt][2] + b20, acc[nt][3] + b21);
            }
        }
        __syncthreads();

        // accumulate over 16 neighbors
        const float* ge = geo_s[cur];
        if (f == 0) {
            #pragma unroll 4
            for (int b = 0; b < 16; b++) {
                int gi = (b0 + b) * 32 + c;
                float r00 = HR[0][b * RADP2 + c];
                acc0 = fmaf(r00, g_in2t[0][gi], acc0);
                acc1 = fmaf(r00, g_in2t[1][gi], acc1);
                acc2 = fmaf(r00, g_in2t[2][gi], acc2);
                acc3 = fmaf(r00, g_in2t[3][gi], acc3);
                acc4 = fmaf(r00, g_in2t[4][gi], acc4);
            }
        } else if (f == 1) {
            #pragma unroll 4
            for (int b = 0; b < 16; b++) {
                const float* gg = ge + b * 12;
                float rx = HR[2][b * RADP2 + c] * gg[8]
                         * p.in0[(size_t)(b0 + b) * 32 + c];
                acc0 = fmaf(rx, gg[3], acc0);
                acc1 = fmaf(rx, gg[4], acc1);
                acc2 = fmaf(rx, gg[5], acc2);
                acc3 = fmaf(rx, gg[6], acc3);
                acc4 = fmaf(rx, gg[7], acc4);
            }
        } else if (f == 2) {
            #pragma unroll 4
            for (int b = 0; b < 16; b++) {
                int gi = (b0 + b) * 32 + c;
                float r00 = HR[0][b * RADP2 + c];
                acc0 = fmaf(r00, g_in1t[0][gi], acc0);
                acc1 = fmaf(r00, g_in1t[1][gi], acc1);
                acc2 = fmaf(r00, g_in1t[2][gi], acc2);
                acc3 = fmaf(r00, p.in0[gi], acc3);
            }
        } else if (f == 3) {
            #pragma unroll 4
            for (int b = 0; b < 16; b++) {
                int gi = (b0 + b) * 32 + c;
                const float* gg = ge + b * 12;
                float mask = gg[8];
                float r10 = HR[3][b * RADP2 + c] * mask;
                float r11 = HR[4][b * RADP2 + c] * mask;
                float v0 = g_in1t[0][gi];
                float v1 = g_in1t[1][gi];
                float v2 = g_in1t[2][gi];
                float ux = gg[0], uy = gg[1], uz = gg[2];
                acc0 = fmaf(r11, uy * v2 - uz * v1, acc0);
                acc1 = fmaf(r11, uz * v0 - ux * v2, acc1);
                acc2 = fmaf(r11, ux * v1 - uy * v0, acc2);
                acc3 = fmaf(r10, ux * v0 + uy * v1 + uz * v2, acc3);
            }
        } else {
            #pragma unroll 4
            for (int b = 0; b < 16; b++) {
                const float* gg = ge + b * 12;
                float rx = HR[1][b * RADP2 + c] * gg[8]
                         * p.in0[(size_t)(b0 + b) * 32 + c];
                acc0 = fmaf(rx, gg[0], acc0);
                acc1 = fmaf(rx, gg[1], acc1);
                acc2 = fmaf(rx, gg[2], acc2);
            }
        }

        cpa_wait0();
        __syncthreads();
    }

    // write partials
    float* out = g_part + (size_t)part * OUTSZ;
    if (f == 0) {
        size_t base = 180224 + (((size_t)(NNODES + a)) * 32 + c) * 5;
        out[base + 0] = acc0; out[base + 1] = acc1; out[base + 2] = acc2;
        out[base + 3] = acc3; out[base + 4] = acc4;
    } else if (f == 1) {
        size_t base = 180224 + (((size_t)a) * 32 + c) * 5;
        out[base + 0] = acc0; out[base + 1] = acc1; out[base + 2] = acc2;
        out[base + 3] = acc3; out[base + 4] = acc4;
    } else if (f == 2) {
        size_t base = 32768 + (((size_t)(NNODES + a)) * 32 + c) * 3;
        out[base + 0] = acc0; out[base + 1] = acc1; out[base + 2] = acc2;
        out[(size_t)a * 32 + c] = acc3;
    } else if (f == 3) {
        size_t base = 32768 + (((size_t)(2 * NNODES + a)) * 32 + c) * 3;
        out[base + 0] = acc0; out[base + 1] = acc1; out[base + 2] = acc2;
        out[16384 + (size_t)a * 32 + c] = acc3;
    } else {
        size_t base = 32768 + (((size_t)a) * 32 + c) * 3;
        out[base + 0] = acc0; out[base + 1] = acc1; out[base + 2] = acc2;
    }
}

__global__ __launch_bounds__(256) void reduce_kernel(float* __restrict__ out) {
    int i = blockIdx.x * 256 + threadIdx.x;
    float s = 0.f;
    #pragma unroll
    for (int k = 0; k < NSPLIT; k++) s += g_part[(size_t)k * OUTSZ + i];
    out[i] = s;
}

extern "C" void kernel_launch(void* const* d_in, const int* in_sizes, int n_in,
                              void* d_out, int out_size) {
    Params p;
    p.in0 = (const float*)d_in[0];
    p.in1 = (const float*)d_in[1];
    p.in2 = (const float*)d_in[2];
    p.rbf = (const float*)d_in[3];
    p.rij = (const float*)d_in[4];
    for (int f = 0; f < 5; f++) {
        p.w1[f] = (const float*)d_in[5 + 4 * f];
        p.b1[f] = (const float*)d_in[6 + 4 * f];
        p.w2[f] = (const float*)d_in[7 + 4 * f];
        p.b2[f] = (const float*)d_in[8 + 4 * f];
    }
    p.out = (float*)d_out;

    prep_kernel<<<(NNODES * NNODES) / 256, 256>>>(p.rij, p.in1, p.in2);
    prep_bfrag<<<10, 512>>>(p);
    tfn_kernel<<<NNODES * NSPLIT, 160>>>(p);
    reduce_kernel<<<OUTSZ / 256, 256>>>(p.out);
}

// round 16
// speedup vs baseline: 2.2641x; 1.1254x over previous
#include <cuda_runtime.h>
#include <cuda_bf16.h>
#include <math.h>
#include <stdint.h>

#define NNODES 512
#define EPSF 1e-8f
#define OUTSZ 344064
#define RADP2 36
#define NSPLIT 8
#define NTILES 4          // tiles per block = (512/NSPLIT)/16

// static device scratch
__device__ __align__(16) float g_in1t[3][NNODES * 32];
__device__ __align__(16) float g_in2t[5][NNODES * 32];
__device__ __align__(16) float g_geo[(size_t)NNODES * NNODES * 12];
__device__ __align__(16) float g_b1frag[10240];   // [0..5119]=hi, [5120..]=lo
__device__ __align__(16) float g_b2frag[10240];
__device__ __align__(16) float g_part[NSPLIT * OUTSZ];

struct Params {
    const float* __restrict__ in0;
    const float* __restrict__ in1;
    const float* __restrict__ in2;
    const float* __restrict__ rbf;
    const float* __restrict__ rij;
    const float* __restrict__ w1[5];
    const float* __restrict__ b1[5];
    const float* __restrict__ w2[5];
    const float* __restrict__ b2[5];
    float* __restrict__ out;
};

__device__ __forceinline__ unsigned tf32r(float x) {
    unsigned u;
    asm("cvt.rna.tf32.f32 %0, %1;" : "=r"(u) : "f"(x));
    return u;
}
__device__ __forceinline__ void mma8(float& c0, float& c1, float& c2, float& c3,
                                     uint4 a, uint2 b) {
    asm("mma.sync.aligned.m16n8k8.row.col.f32.tf32.tf32.f32 "
        "{%0,%1,%2,%3},{%4,%5,%6,%7},{%8,%9},{%0,%1,%2,%3};"
        : "+f"(c0), "+f"(c1), "+f"(c2), "+f"(c3)
        : "r"(a.x), "r"(a.y), "r"(a.z), "r"(a.w), "r"(b.x), "r"(b.y));
}
__device__ __forceinline__ uint2 ldg64v(const float* p) {
    uint2 v;
    asm volatile("ld.global.nc.v2.u32 {%0,%1}, [%2];"
                 : "=r"(v.x), "=r"(v.y) : "l"(p));
    return v;
}
__device__ __forceinline__ void cpa16(void* dst, const void* src) {
    unsigned int d = (unsigned int)__cvta_generic_to_shared(dst);
    asm volatile("cp.async.cg.shared.global [%0], [%1], 16;" :: "r"(d), "l"(src));
}
__device__ __forceinline__ void cpa_commit() { asm volatile("cp.async.commit_group;"); }
__device__ __forceinline__ void cpa_wait0()  { asm volatile("cp.async.wait_group 0;" ::: "memory"); }

__global__ __launch_bounds__(256) void prep_kernel(
    const float* __restrict__ rij,
    const float* __restrict__ in1,
    const float* __restrict__ in2)
{
    int idx = blockIdx.x * 256 + threadIdx.x;
    if (idx < NNODES * 32) {
        #pragma unroll
        for (int i = 0; i < 3; i++) g_in1t[i][idx] = in1[idx * 3 + i];
        #pragma unroll
        for (int i = 0; i < 5; i++) g_in2t[i][idx] = in2[idx * 5 + i];
    }
    const float inv_c2 = 0.28867513459481287f;
    float rx = rij[idx * 3 + 0];
    float ry = rij[idx * 3 + 1];
    float rz = rij[idx * 3 + 2];
    float n2 = rx * rx + ry * ry + rz * rz;
    float nrm = sqrtf(n2);
    float invn = 1.f / (nrm + EPSF);
    float mask = (nrm >= EPSF) ? 1.f : 0.f;
    float ir2 = 1.f / fmaxf(n2, EPSF);
    float* g = g_geo + (size_t)idx * 12;
    g[0] = rx * invn; g[1] = ry * invn; g[2] = rz * invn;
    g[3] = rx * ry * ir2;
    g[4] = ry * rz * ir2;
    g[5] = (2.f * rz * rz - rx * rx - ry * ry) * ir2 * inv_c2;
    g[6] = rz * rx * ir2;
    g[7] = (rx * rx - ry * ry) * 0.5f * ir2;
    g[8] = mask;
    g[9] = 0.f; g[10] = 0.f; g[11] = 0.f;
}

// tf32 weight fragments, error-compensated: hi + lo per entry.
__global__ void prep_bfrag(Params p) {
    int idx = blockIdx.x * 512 + threadIdx.x;
    if (idx >= 5120) return;
    int i    = idx & 1;
    int lane = (idx >> 1) & 31;
    int nt   = (idx >> 6) & 3;
    int kt   = (idx >> 8) & 3;
    int f    = idx >> 10;
    int g = lane >> 2, t = lane & 3;
    int rw = nt * 8 + g;
    int cw = kt * 8 + t + 4 * i;
    float w1 = p.w1[f][rw * 32 + cw];
    float h1 = __uint_as_float(tf32r(w1));
    g_b1frag[idx]        = h1;
    g_b1frag[idx + 5120] = __uint_as_float(tf32r(w1 - h1));
    float w2 = p.w2[f][rw * 32 + cw];
    float h2 = __uint_as_float(tf32r(w2));
    g_b2frag[idx]        = h2;
    g_b2frag[idx + 5120] = __uint_as_float(tf32r(w2 - h2));
}

// Fused: 4096 blocks (a, eighth). 5 warps = 5 filters. 4 tiles x 16 neighbors.
// A/H stored hi-only; weights carry the hi/lo compensation.
__global__ __launch_bounds__(160, 5) void tfn_kernel(Params p) {
    __shared__ float raw_s[2][512];
    __shared__ float geo_s[2][192];
    __shared__ float As[512];       // A hi frags
    __shared__ float HR[5][576];    // Hh frags [0..511]; rad overwrites [b*36+c]
    __shared__ float bias_s[5][64];

    const int tid  = threadIdx.x;
    const int lane = tid & 31;
    const int f    = tid >> 5;
    const int a    = blockIdx.x >> 3;
    const int part = blockIdx.x & 7;
    const int bstart = part * 64;
    const int c    = lane;
    const int g    = lane >> 2;
    const int t4   = lane & 3;

    bias_s[f][lane]      = p.b1[f][lane];
    bias_s[f][32 + lane] = p.b2[f][lane];

    float acc0 = 0.f, acc1 = 0.f, acc2 = 0.f, acc3 = 0.f, acc4 = 0.f;

    const float* rbase = p.rbf + ((size_t)a * NNODES + bstart) * 32;
    const float* gbase = g_geo + ((size_t)a * NNODES + bstart) * 12;

    // preload tile 0
    if (tid < 128) {
        cpa16(&raw_s[0][tid * 4], rbase + tid * 4);
    } else {
        int q = tid - 128;
        cpa16(&geo_s[0][q * 4], gbase + q * 4);
        if (q < 16) cpa16(&geo_s[0][(q + 32) * 4], gbase + (q + 32) * 4);
    }
    cpa_commit();
    cpa_wait0();
    __syncthreads();

    for (int t = 0; t < NTILES; t++) {
        const int cur = t & 1;
        const int b0 = bstart + t * 16;

        // prefetch tile t+1
        if (t < NTILES - 1) {
            const float* rsrc = rbase + (size_t)(t + 1) * 512;
            const float* gsrc = gbase + (size_t)(t + 1) * 192;
            if (tid < 128) {
                cpa16(&raw_s[cur ^ 1][tid * 4], rsrc + tid * 4);
            } else {
                int q = tid - 128;
                cpa16(&geo_s[cur ^ 1][q * 4], gsrc + q * 4);
                if (q < 16) cpa16(&geo_s[cur ^ 1][(q + 32) * 4], gsrc + (q + 32) * 4);
            }
        }
        cpa_commit();

        // split raw rbf -> tf32 hi A-frags (hi-only)
        if (tid < 128) {
            float4 rv = *(const float4*)&raw_s[cur][tid * 4];
            int nb = tid >> 3;
            int r0 = (tid & 7) * 4;
            float xv[4] = {rv.x, rv.y, rv.z, rv.w};
            #pragma unroll
            for (int j = 0; j < 4; j++) {
                int r = r0 + j;
                int kt = r >> 3, rm = r & 7;
                int tq = rm & 3, dl = rm >> 2;
                int off = kt * 128 + ((nb & 7) * 4 + tq) * 4 + (nb >> 3) + 2 * dl;
                As[off] = __uint_as_float(tf32r(xv[j]));
            }
        }
        __syncthreads();

        // stage1: H = relu(b1 + rbf @ W1^T) -- weight hi/lo pipelined
        {
            float acc[4][4];
            #pragma unroll
            for (int nt = 0; nt < 4; nt++) { acc[nt][0]=0.f; acc[nt][1]=0.f; acc[nt][2]=0.f; acc[nt][3]=0.f; }
            uint2 bwh[4], bwl[4];
            #pragma unroll
            for (int nt = 0; nt < 4; nt++) {
                int base = ((f * 16 + nt) * 64) + lane * 2;
                bwh[nt] = ldg64v(&g_b1frag[base]);
                bwl[nt] = ldg64v(&g_b1frag[base + 5120]);
            }
            #pragma unroll
            for (int kt = 0; kt < 4; kt++) {
                uint2 nh[4], nl[4];
                if (kt < 3) {
                    #pragma unroll
                    for (int nt = 0; nt < 4; nt++) {
                        int base = (((f * 4 + kt + 1) * 4 + nt) * 64) + lane * 2;
                        nh[nt] = ldg64v(&g_b1frag[base]);
                        nl[nt] = ldg64v(&g_b1frag[base + 5120]);
                    }
                }
                uint4 ah = *(const uint4*)&As[kt * 128 + lane * 4];
                #pragma unroll
                for (int nt = 0; nt < 4; nt++) {
                    mma8(acc[nt][0], acc[nt][1], acc[nt][2], acc[nt][3], ah, bwh[nt]);
                    mma8(acc[nt][0], acc[nt][1], acc[nt][2], acc[nt][3], ah, bwl[nt]);
                }
                if (kt < 3) {
                    #pragma unroll
                    for (int nt = 0; nt < 4; nt++) { bwh[nt] = nh[nt]; bwl[nt] = nl[nt]; }
                }
            }
            float* Hh = HR[f];
            #pragma unroll
            for (int nt = 0; nt < 4; nt++) {
                #pragma unroll
                for (int e = 0; e < 4; e++) {
                    int row = g + (e >= 2 ? 8 : 0);
                    int dc  = e & 1;
                    float bb = bias_s[f][nt * 8 + 2 * t4 + dc];
                    float h = fmaxf(acc[nt][e] + bb, 0.f);
                    int rm = 2 * t4 + dc;
                    int tq = rm & 3, dl = rm >> 2;
                    int off = nt * 128 + ((row & 7) * 4 + tq) * 4 + (row >> 3) + 2 * dl;
                    Hh[off] = __uint_as_float(tf32r(h));
                }
            }
        }
        __syncwarp();

        // stage2: rad = b2 + H @ W2^T -- weight hi/lo pipelined
        {
            float acc[4][4];
            #pragma unroll
            for (int nt = 0; nt < 4; nt++) { acc[nt][0]=0.f; acc[nt][1]=0.f; acc[nt][2]=0.f; acc[nt][3]=0.f; }
            const float* Hh = HR[f];
            uint2 bwh[4], bwl[4];
            #pragma unroll
            for (int nt = 0; nt < 4; nt++) {
                int base = ((f * 16 + nt) * 64) + lane * 2;
                bwh[nt] = ldg64v(&g_b2frag[base]);
                bwl[nt] = ldg64v(&g_b2frag[base + 5120]);
            }
            #pragma unroll
            for (int kt = 0; kt < 4; kt++) {
                uint2 nh[4], nl[4];
                if (kt < 3) {
                    #pragma unroll
                    for (int nt = 0; nt < 4; nt++) {
                        int base = (((f * 4 + kt + 1) * 4 + nt) * 64) + lane * 2;
                        nh[nt] = ldg64v(&g_b2frag[base]);
                        nl[nt] = ldg64v(&g_b2frag[base + 5120]);
                    }
                }
                uint4 ah = *(const uint4*)&Hh[kt * 128 + lane * 4];
                #pragma unroll
                for (int nt = 0; nt < 4; nt++) {
                    mma8(acc[nt][0], acc[nt][1], acc[nt][2], acc[nt][3], ah, bwh[nt]);
                    mma8(acc[nt][0], acc[nt][1], acc[nt][2], acc[nt][3], ah, bwl[nt]);
                }
                if (kt < 3) {
                    #pragma unroll
                    for (int nt = 0; nt < 4; nt++) { bwh[nt] = nh[nt]; bwl[nt] = nl[nt]; }
                }
            }
            #pragma unroll
            for (int nt = 0; nt < 4; nt++) {
                int colw = nt * 8 + 2 * t4;
                float b20 = bias_s[f][32 + colw];
                float b21 = bias_s[f][32 + colw + 1];
                *(float2*)&HR[f][g * RADP2 + colw] =
                    make_float2(acc[nt][0] + b20, acc[nt][1] + b21);
                *(float2*)&HR[f][(g + 8) * RADP2 + colw] =
                    make_float2(acc[nt][2] + b20, acc[nt][3] + b21);
            }
        }
        __syncthreads();

        // accumulate over 16 neighbors (full unroll -> deep LDG batching)
        const float* ge = geo_s[cur];
        if (f == 0) {
            #pragma unroll
            for (int b = 0; b < 16; b++) {
                int gi = (b0 + b) * 32 + c;
                float r00 = HR[0][b * RADP2 + c];
                acc0 = fmaf(r00, g_in2t[0][gi], acc0);
                acc1 = fmaf(r00, g_in2t[1][gi], acc1);
                acc2 = fmaf(r00, g_in2t[2][gi], acc2);
                acc3 = fmaf(r00, g_in2t[3][gi], acc3);
                acc4 = fmaf(r00, g_in2t[4][gi], acc4);
            }
        } else if (f == 1) {
            #pragma unroll
            for (int b = 0; b < 16; b++) {
                const float* gg = ge + b * 12;
                float rx = HR[2][b * RADP2 + c] * gg[8]
                         * p.in0[(size_t)(b0 + b) * 32 + c];
                acc0 = fmaf(rx, gg[3], acc0);
                acc1 = fmaf(rx, gg[4], acc1);
                acc2 = fmaf(rx, gg[5], acc2);
                acc3 = fmaf(rx, gg[6], acc3);
                acc4 = fmaf(rx, gg[7], acc4);
            }
        } else if (f == 2) {
            #pragma unroll
            for (int b = 0; b < 16; b++) {
                int gi = (b0 + b) * 32 + c;
                float r00 = HR[0][b * RADP2 + c];
                acc0 = fmaf(r00, g_in1t[0][gi], acc0);
                acc1 = fmaf(r00, g_in1t[1][gi], acc1);
                acc2 = fmaf(r00, g_in1t[2][gi], acc2);
                acc3 = fmaf(r00, p.in0[gi], acc3);
            }
        } else if (f == 3) {
            #pragma unroll
            for (int b = 0; b < 16; b++) {
                int gi = (b0 + b) * 32 + c;
                const float* gg = ge + b * 12;
                float mask = gg[8];
                float r10 = HR[3][b * RADP2 + c] * mask;
                float r11 = HR[4][b * RADP2 + c] * mask;
                float v0 = g_in1t[0][gi];
                float v1 = g_in1t[1][gi];
                float v2 = g_in1t[2][gi];
                float ux = gg[0], uy = gg[1], uz = gg[2];
                acc0 = fmaf(r11, uy * v2 - uz * v1, acc0);
                acc1 = fmaf(r11, uz * v0 - ux * v2, acc1);
                acc2 = fmaf(r11, ux * v1 - uy * v0, acc2);
                acc3 = fmaf(r10, ux * v0 + uy * v1 + uz * v2, acc3);
            }
        } else {
            #pragma unroll
            for (int b = 0; b < 16; b++) {
                const float* gg = ge + b * 12;
                float rx = HR[1][b * RADP2 + c] * gg[8]
                         * p.in0[(size_t)(b0 + b) * 32 + c];
                acc0 = fmaf(rx, gg[0], acc0);
                acc1 = fmaf(rx, gg[1], acc1);
                acc2 = fmaf(rx, gg[2], acc2);
            }
        }

        cpa_wait0();
        __syncthreads();
    }

    // write partials
    float* out = g_part + (size_t)part * OUTSZ;
    if (f == 0) {
        size_t base = 180224 + (((size_t)(NNODES + a)) * 32 + c) * 5;
        out[base + 0] = acc0; out[base + 1] = acc1; out[base + 2] = acc2;
        out[base + 3] = acc3; out[base + 4] = acc4;
    } else if (f == 1) {
        size_t base = 180224 + (((size_t)a) * 32 + c) * 5;
        out[base + 0] = acc0; out[base + 1] = acc1; out[base + 2] = acc2;
        out[base + 3] = acc3; out[base + 4] = acc4;
    } else if (f == 2) {
        size_t base = 32768 + (((size_t)(NNODES + a)) * 32 + c) * 3;
        out[base + 0] = acc0; out[base + 1] = acc1; out[base + 2] = acc2;
        out[(size_t)a * 32 + c] = acc3;
    } else if (f == 3) {
        size_t base = 32768 + (((size_t)(2 * NNODES + a)) * 32 + c) * 3;
        out[base + 0] = acc0; out[base + 1] = acc1; out[base + 2] = acc2;
        out[16384 + (size_t)a * 32 + c] = acc3;
    } else {
        size_t base = 32768 + (((size_t)a) * 32 + c) * 3;
        out[base + 0] = acc0; out[base + 1] = acc1; out[base + 2] = acc2;
    }
}

__global__ __launch_bounds__(256) void reduce_kernel(float* __restrict__ out) {
    int i = blockIdx.x * 256 + threadIdx.x;
    float s = 0.f;
    #pragma unroll
    for (int k = 0; k < NSPLIT; k++) s += g_part[(size_t)k * OUTSZ + i];
    out[i] = s;
}

extern "C" void kernel_launch(void* const* d_in, const int* in_sizes, int n_in,
                              void* d_out, int out_size) {
    Params p;
    p.in0 = (const float*)d_in[0];
    p.in1 = (const float*)d_in[1];
    p.in2 = (const float*)d_in[2];
    p.rbf = (const float*)d_in[3];
    p.rij = (const float*)d_in[4];
    for (int f = 0; f < 5; f++) {
        p.w1[f] = (const float*)d_in[5 + 4 * f];
        p.b1[f] = (const float*)d_in[6 + 4 * f];
        p.w2[f] = (const float*)d_in[7 + 4 * f];
        p.b2[f] = (const float*)d_in[8 + 4 * f];
    }
    p.out = (float*)d_out;

    prep_kernel<<<(NNODES * NNODES) / 256, 256>>>(p.rij, p.in1, p.in2);
    prep_bfrag<<<10, 512>>>(p);
    tfn_kernel<<<NNODES * NSPLIT, 160>>>(p);
    reduce_kernel<<<OUTSZ / 256, 256>>>(p.out);
}